// round 1
// baseline (speedup 1.0000x reference)
#include <cuda_runtime.h>
#include <math.h>

#define TT 2048
#define HH 1024
#define FF 512
#define EE 32
#define KSEL 4
#define NSLOT (TT * KSEL)

// ---- scratch (static device globals: allocation-free per harness rules) ----
__device__ int   g_sel[NSLOT];
__device__ float g_wt[NSLOT];
__device__ int   g_cnt[EE];
__device__ int   g_off[EE];
__device__ int   g_cur[EE];
__device__ int   g_slot_tok[NSLOT];
__device__ float g_slot_wt[NSLOT];
__device__ float g_hbuf[(size_t)NSLOT * FF];   // 16 MB: gate*up activations, pre-scaled by routing weight

// ---------------------------------------------------------------------------
__global__ void k_init() {
    if (threadIdx.x < EE) g_cnt[threadIdx.x] = 0;
}

// Router: logits = x @ w_router^T, top-4, softmax over selected.
// One block per token, 128 threads (4 warps x 8 experts each).
__global__ __launch_bounds__(128) void k_router(const float* __restrict__ rin,
                                                const float* __restrict__ wr,
                                                float* __restrict__ logits) {
    __shared__ float xs[HH];
    __shared__ float lg[EE];
    int t = blockIdx.x;
    int tid = threadIdx.x;
    const float* x = rin + (size_t)t * HH;
    for (int i = tid * 4; i < HH; i += 128 * 4)
        *(float4*)&xs[i] = *(const float4*)&x[i];
    __syncthreads();
    int warp = tid >> 5, lane = tid & 31;
    for (int ei = 0; ei < 8; ei++) {
        int e = warp * 8 + ei;
        const float* w = wr + (size_t)e * HH;
        float s = 0.f;
        #pragma unroll 8
        for (int j = lane; j < HH; j += 32) s += xs[j] * w[j];
        #pragma unroll
        for (int o = 16; o; o >>= 1) s += __shfl_xor_sync(0xffffffffu, s, o);
        if (lane == 0) lg[e] = s;
    }
    __syncthreads();
    if (tid < EE) logits[(size_t)t * EE + tid] = lg[tid];
    if (tid == 0) {
        int sel[KSEL]; float val[KSEL];
        unsigned msk = 0u;
        for (int k = 0; k < KSEL; k++) {
            float best = -INFINITY; int bi = 0;
            for (int e = 0; e < EE; e++)
                if (!((msk >> e) & 1u) && lg[e] > best) { best = lg[e]; bi = e; }
            msk |= 1u << bi; sel[k] = bi; val[k] = best;
        }
        float mx = val[0];             // first pick is the global max
        float ex[KSEL], se = 0.f;
        for (int k = 0; k < KSEL; k++) { ex[k] = expf(val[k] - mx); se += ex[k]; }
        float inv = 1.f / se;
        for (int k = 0; k < KSEL; k++) {
            g_sel[t * KSEL + k] = sel[k];
            g_wt[t * KSEL + k]  = ex[k] * inv;
            atomicAdd(&g_cnt[sel[k]], 1);
        }
    }
}

// Exclusive scan over 32 expert counts.
__global__ void k_scan() {
    int e = threadIdx.x;               // 32 threads
    int c = g_cnt[e];
    int s = c;
    #pragma unroll
    for (int o = 1; o < 32; o <<= 1) {
        int v = __shfl_up_sync(0xffffffffu, s, o);
        if (e >= o) s += v;
    }
    g_off[e] = s - c;
    g_cur[e] = s - c;
}

// Scatter (token, weight) into expert-sorted compact slot lists.
__global__ void k_scatter() {
    int t = blockIdx.x * blockDim.x + threadIdx.x;
    if (t >= TT) return;
    #pragma unroll
    for (int k = 0; k < KSEL; k++) {
        int e = g_sel[t * KSEL + k];
        int p = atomicAdd(&g_cur[e], 1);
        g_slot_tok[p] = t;
        g_slot_wt[p]  = g_wt[t * KSEL + k];
    }
}

// Gate/Up GEMM: per block = (expert, 64-token tile, 64-f tile).
// h[slot][f] = relu(x@Wg^T) * (x@Wu^T) * routing_weight
__global__ __launch_bounds__(256) void k_gateup(const float* __restrict__ hs,
                                                const float* __restrict__ wg,
                                                const float* __restrict__ wu) {
    __shared__ float As[32][64];
    __shared__ float Bg[32][64];
    __shared__ float Bu[32][64];
    __shared__ int   stok[64];
    __shared__ float swt[64];
    int e   = blockIdx.x;
    int n_e = g_cnt[e];
    int row0 = blockIdx.y * 64;
    if (row0 >= n_e) return;
    int base = g_off[e];
    int rem  = n_e - row0; if (rem > 64) rem = 64;
    int tid  = threadIdx.x;
    if (tid < 64) {
        int m = tid < rem ? tid : rem - 1;   // clamp partial tile
        stok[tid] = g_slot_tok[base + row0 + m];
        swt[tid]  = g_slot_wt[base + row0 + m];
    }
    __syncthreads();
    int f0 = blockIdx.z * 64;
    int tx = tid & 15, ty = tid >> 4;
    int mld = tid & 63, q = tid >> 6;        // loader mapping: row mld, k-chunk 8q
    const float* xrow = hs + (size_t)stok[mld] * HH + 8 * q;
    const float* grow = wg + ((size_t)e * FF + f0 + mld) * HH + 8 * q;
    const float* urow = wu + ((size_t)e * FF + f0 + mld) * HH + 8 * q;
    float ag[4][4] = {}, au[4][4] = {};
    for (int k0 = 0; k0 < HH; k0 += 32) {
        float4 a0 = *(const float4*)(xrow + k0);
        float4 a1 = *(const float4*)(xrow + k0 + 4);
        float4 g0 = *(const float4*)(grow + k0);
        float4 g1 = *(const float4*)(grow + k0 + 4);
        float4 u0 = *(const float4*)(urow + k0);
        float4 u1 = *(const float4*)(urow + k0 + 4);
        __syncthreads();
        int kq = 8 * q;
        As[kq+0][mld]=a0.x; As[kq+1][mld]=a0.y; As[kq+2][mld]=a0.z; As[kq+3][mld]=a0.w;
        As[kq+4][mld]=a1.x; As[kq+5][mld]=a1.y; As[kq+6][mld]=a1.z; As[kq+7][mld]=a1.w;
        Bg[kq+0][mld]=g0.x; Bg[kq+1][mld]=g0.y; Bg[kq+2][mld]=g0.z; Bg[kq+3][mld]=g0.w;
        Bg[kq+4][mld]=g1.x; Bg[kq+5][mld]=g1.y; Bg[kq+6][mld]=g1.z; Bg[kq+7][mld]=g1.w;
        Bu[kq+0][mld]=u0.x; Bu[kq+1][mld]=u0.y; Bu[kq+2][mld]=u0.z; Bu[kq+3][mld]=u0.w;
        Bu[kq+4][mld]=u1.x; Bu[kq+5][mld]=u1.y; Bu[kq+6][mld]=u1.z; Bu[kq+7][mld]=u1.w;
        __syncthreads();
        #pragma unroll 8
        for (int kk = 0; kk < 32; kk++) {
            float4 av = *(float4*)&As[kk][ty * 4];
            float4 gv = *(float4*)&Bg[kk][tx * 4];
            float4 uv = *(float4*)&Bu[kk][tx * 4];
            float a[4]  = {av.x, av.y, av.z, av.w};
            float gb[4] = {gv.x, gv.y, gv.z, gv.w};
            float ub[4] = {uv.x, uv.y, uv.z, uv.w};
            #pragma unroll
            for (int i = 0; i < 4; i++)
                #pragma unroll
                for (int j = 0; j < 4; j++) {
                    ag[i][j] += a[i] * gb[j];
                    au[i][j] += a[i] * ub[j];
                }
        }
    }
    #pragma unroll
    for (int i = 0; i < 4; i++) {
        int m = ty * 4 + i;
        if (m < rem) {
            float w = swt[m];
            int slot = base + row0 + m;
            float4 o;
            o.x = fmaxf(ag[i][0], 0.f) * au[i][0] * w;
            o.y = fmaxf(ag[i][1], 0.f) * au[i][1] * w;
            o.z = fmaxf(ag[i][2], 0.f) * au[i][2] * w;
            o.w = fmaxf(ag[i][3], 0.f) * au[i][3] * w;
            *(float4*)&g_hbuf[(size_t)slot * FF + f0 + tx * 4] = o;
        }
    }
}

// Down GEMM: out[tok] += h[slot] @ Wd^T (weight already folded into h).
__global__ __launch_bounds__(256) void k_down(const float* __restrict__ wd,
                                              float* __restrict__ out) {
    __shared__ float As[32][64];
    __shared__ float Bd[32][64];
    __shared__ int   stok[64];
    int e   = blockIdx.x;
    int n_e = g_cnt[e];
    int row0 = blockIdx.y * 64;
    if (row0 >= n_e) return;
    int base = g_off[e];
    int rem  = n_e - row0; if (rem > 64) rem = 64;
    int tid  = threadIdx.x;
    if (tid < 64) {
        int m = tid < rem ? tid : rem - 1;
        stok[tid] = g_slot_tok[base + row0 + m];
    }
    __syncthreads();
    int h0 = blockIdx.z * 64;
    int tx = tid & 15, ty = tid >> 4;
    int mld = tid & 63, q = tid >> 6;
    int mslot = mld < rem ? mld : rem - 1;
    const float* hrow = g_hbuf + (size_t)(base + row0 + mslot) * FF + 8 * q;
    const float* drow = wd + ((size_t)e * HH + h0 + mld) * FF + 8 * q;
    float ac[4][4] = {};
    for (int k0 = 0; k0 < FF; k0 += 32) {
        float4 a0 = *(const float4*)(hrow + k0);
        float4 a1 = *(const float4*)(hrow + k0 + 4);
        float4 b0 = *(const float4*)(drow + k0);
        float4 b1 = *(const float4*)(drow + k0 + 4);
        __syncthreads();
        int kq = 8 * q;
        As[kq+0][mld]=a0.x; As[kq+1][mld]=a0.y; As[kq+2][mld]=a0.z; As[kq+3][mld]=a0.w;
        As[kq+4][mld]=a1.x; As[kq+5][mld]=a1.y; As[kq+6][mld]=a1.z; As[kq+7][mld]=a1.w;
        Bd[kq+0][mld]=b0.x; Bd[kq+1][mld]=b0.y; Bd[kq+2][mld]=b0.z; Bd[kq+3][mld]=b0.w;
        Bd[kq+4][mld]=b1.x; Bd[kq+5][mld]=b1.y; Bd[kq+6][mld]=b1.z; Bd[kq+7][mld]=b1.w;
        __syncthreads();
        #pragma unroll 8
        for (int kk = 0; kk < 32; kk++) {
            float4 av = *(float4*)&As[kk][ty * 4];
            float4 bv = *(float4*)&Bd[kk][tx * 4];
            float a[4] = {av.x, av.y, av.z, av.w};
            float b[4] = {bv.x, bv.y, bv.z, bv.w};
            #pragma unroll
            for (int i = 0; i < 4; i++)
                #pragma unroll
                for (int j = 0; j < 4; j++)
                    ac[i][j] += a[i] * b[j];
        }
    }
    #pragma unroll
    for (int i = 0; i < 4; i++) {
        int m = ty * 4 + i;
        if (m < rem) {
            int tok = stok[m];
            float* op = out + (size_t)tok * HH + h0 + tx * 4;
            atomicAdd(op + 0, ac[i][0]);
            atomicAdd(op + 1, ac[i][1]);
            atomicAdd(op + 2, ac[i][2]);
            atomicAdd(op + 3, ac[i][3]);
        }
    }
}

// ---------------------------------------------------------------------------
extern "C" void kernel_launch(void* const* d_in, const int* in_sizes, int n_in,
                              void* d_out, int out_size) {
    const float* rin = (const float*)d_in[0];   // router_input [T,H]
    const float* hs  = (const float*)d_in[1];   // hidden_states [T,H]
    const float* wr  = (const float*)d_in[2];   // w_router [E,H]
    const float* wg  = (const float*)d_in[3];   // w_gate [E,F,H]
    const float* wu  = (const float*)d_in[4];   // w_up   [E,F,H]
    const float* wd  = (const float*)d_in[5];   // w_down [E,H,F]
    float* out    = (float*)d_out;                    // out [T,H]
    float* logits = out + (size_t)TT * HH;            // router_logits [T,E]

    cudaMemsetAsync(out, 0, (size_t)TT * HH * sizeof(float), 0);
    k_init<<<1, 32>>>();
    k_router<<<TT, 128>>>(rin, wr, logits);
    k_scan<<<1, 32>>>();
    k_scatter<<<(TT + 255) / 256, 256>>>();
    k_gateup<<<dim3(EE, TT / 64, FF / 64), 256>>>(hs, wg, wu);
    k_down<<<dim3(EE, TT / 64, HH / 64), 256>>>(wd, out);
}

// round 4
// speedup vs baseline: 3.0062x; 3.0062x over previous
#include <cuda_runtime.h>
#include <cstdint>
#include <math.h>

#define TT 2048
#define HH 1024
#define FF 512
#define EE 32
#define KSEL 4
#define NSLOT (TT * KSEL)

// ---- scratch ----
__device__ int   g_sel[NSLOT];
__device__ float g_wt[NSLOT];
__device__ int   g_cnt[EE];
__device__ int   g_off[EE];
__device__ int   g_cur[EE];
__device__ int   g_slot_tok[NSLOT];
__device__ float g_slot_wt[NSLOT];
__device__ float g_hbuf[(size_t)NSLOT * FF];   // gate*up activations, pre-scaled

// ---- helpers ----
__device__ __forceinline__ uint32_t smem_u32(const void* p) {
    uint32_t a;
    asm("{ .reg .u64 t; cvta.to.shared.u64 t, %1; cvt.u32.u64 %0, t; }" : "=r"(a) : "l"(p));
    return a;
}
// fp32 -> tf32 round-to-nearest (add half-ulp of the 10-bit mantissa; HW truncates)
__device__ __forceinline__ float4 rna4(float4 v) {
    uint4 u = *(uint4*)&v;
    u.x += 0x1000u; u.y += 0x1000u; u.z += 0x1000u; u.w += 0x1000u;
    return *(float4*)&u;
}
__device__ __forceinline__ void ldm_x4(uint32_t* r, uint32_t addr) {
    asm volatile("ldmatrix.sync.aligned.m8n8.x4.shared.b16 {%0,%1,%2,%3}, [%4];"
                 : "=r"(r[0]), "=r"(r[1]), "=r"(r[2]), "=r"(r[3]) : "r"(addr));
}
__device__ __forceinline__ void mma8(float* c, const uint32_t* a, uint32_t b0, uint32_t b1) {
    asm volatile("mma.sync.aligned.m16n8k8.row.col.f32.tf32.tf32.f32 "
                 "{%0,%1,%2,%3}, {%4,%5,%6,%7}, {%8,%9}, {%0,%1,%2,%3};"
                 : "+f"(c[0]), "+f"(c[1]), "+f"(c[2]), "+f"(c[3])
                 : "r"(a[0]), "r"(a[1]), "r"(a[2]), "r"(a[3]), "r"(b0), "r"(b1));
}

// smem word layout (dynamic): [0]stok[128] [128]swt[128] [256] buffers
#define STRIDE 36                    // padded row stride in words (32 data + 4 pad)
#define A_WORDS (128 * STRIDE)       // 4608
#define STOK_W 0
#define SWT_W 128
#define BUF_W 256
#define BUFSTRIDE 9216               // words per double-buffer stage (A + B tiles)
#define SMEM_BYTES ((BUF_W + 2 * BUFSTRIDE) * 4)   // 74752

// ---------------------------------------------------------------------------
__global__ void k_init() { if (threadIdx.x < EE) g_cnt[threadIdx.x] = 0; }

__global__ __launch_bounds__(128) void k_router(const float* __restrict__ rin,
                                                const float* __restrict__ wr,
                                                float* __restrict__ logits) {
    __shared__ float xs[HH];
    __shared__ float lg[EE];
    int t = blockIdx.x;
    int tid = threadIdx.x;
    const float* x = rin + (size_t)t * HH;
    for (int i = tid * 4; i < HH; i += 128 * 4)
        *(float4*)&xs[i] = *(const float4*)&x[i];
    __syncthreads();
    int warp = tid >> 5, lane = tid & 31;
    for (int ei = 0; ei < 8; ei++) {
        int e = warp * 8 + ei;
        const float* w = wr + (size_t)e * HH;
        float s = 0.f;
        #pragma unroll 8
        for (int j = lane; j < HH; j += 32) s += xs[j] * w[j];
        #pragma unroll
        for (int o = 16; o; o >>= 1) s += __shfl_xor_sync(0xffffffffu, s, o);
        if (lane == 0) lg[e] = s;
    }
    __syncthreads();
    if (tid < EE) logits[(size_t)t * EE + tid] = lg[tid];
    if (tid == 0) {
        int sel[KSEL]; float val[KSEL];
        unsigned msk = 0u;
        for (int k = 0; k < KSEL; k++) {
            float best = -INFINITY; int bi = 0;
            for (int e = 0; e < EE; e++)
                if (!((msk >> e) & 1u) && lg[e] > best) { best = lg[e]; bi = e; }
            msk |= 1u << bi; sel[k] = bi; val[k] = best;
        }
        float mx = val[0];
        float ex[KSEL], se = 0.f;
        for (int k = 0; k < KSEL; k++) { ex[k] = expf(val[k] - mx); se += ex[k]; }
        float inv = 1.f / se;
        for (int k = 0; k < KSEL; k++) {
            g_sel[t * KSEL + k] = sel[k];
            g_wt[t * KSEL + k]  = ex[k] * inv;
            atomicAdd(&g_cnt[sel[k]], 1);
        }
    }
}

__global__ void k_scan() {
    int e = threadIdx.x;
    int c = g_cnt[e];
    int s = c;
    #pragma unroll
    for (int o = 1; o < 32; o <<= 1) {
        int v = __shfl_up_sync(0xffffffffu, s, o);
        if (e >= o) s += v;
    }
    g_off[e] = s - c;
    g_cur[e] = s - c;
}

__global__ void k_scatter() {
    int t = blockIdx.x * blockDim.x + threadIdx.x;
    if (t >= TT) return;
    #pragma unroll
    for (int k = 0; k < KSEL; k++) {
        int e = g_sel[t * KSEL + k];
        int p = atomicAdd(&g_cur[e], 1);
        g_slot_tok[p] = t;
        g_slot_wt[p]  = g_wt[t * KSEL + k];
    }
}

// ---------------------------------------------------------------------------
// gate/up GEMM (tf32 mma.sync): block = (expert, 128-slot tile, 64-f tile)
// Each warp: M64 x 16 f-cols, computing gate AND up accumulators.
__global__ __launch_bounds__(256) void k_gateup(const float* __restrict__ hs,
                                                const float* __restrict__ wg,
                                                const float* __restrict__ wu) {
    extern __shared__ float sm[];
    const int e = blockIdx.x;
    const int n_e = g_cnt[e];
    const int row0 = blockIdx.y * 128;
    if (row0 >= n_e) return;
    const int base = g_off[e];
    int rem = n_e - row0; if (rem > 128) rem = 128;
    const int f0 = blockIdx.z * 64;
    const int tid = threadIdx.x;
    const int wid = tid >> 5, lid = tid & 31;
    const int wm = wid & 1, wn = wid >> 1;        // 2 x 4 warp grid

    int*   stok = (int*)&sm[STOK_W];
    float* swt  = &sm[SWT_W];
    if (tid < 128) {
        int m = tid < rem ? tid : rem - 1;
        stok[tid] = g_slot_tok[base + row0 + m];
        swt[tid]  = g_slot_wt[base + row0 + m];
    }
    __syncthreads();

    // loader mapping
    const int arow = tid >> 1, aseg = (tid & 1) * 16;          // A: 128 x 32 per chunk
    const int brow = tid >> 2, bseg = (tid & 3) * 8;           // B: 64 x 32 per chunk
    const float* ap = hs + (size_t)stok[arow] * HH + aseg;
    const float* gp = wg + ((size_t)e * FF + f0 + brow) * HH + bseg;
    const float* up = wu + ((size_t)e * FF + f0 + brow) * HH + bseg;

    // ldmatrix per-lane offsets (bytes within tile)
    const uint32_t smb = smem_u32(sm);
    const int rl  = (lid & 7) + 8 * ((lid >> 3) & 1);
    const int clA = 4 * (lid >> 4);
    const uint32_t laneA = (uint32_t)(rl * STRIDE + clA) * 4;
    const int rbl = (lid & 7) + 8 * (lid >> 4);
    const int clB = 4 * ((lid >> 3) & 1);
    const uint32_t laneB = (uint32_t)(rbl * STRIDE + clB) * 4;

    float cg[4][2][4] = {}, cu[4][2][4] = {};
    float4 lA[4], lG[2], lU[2];

    // prefetch chunk 0
    #pragma unroll
    for (int j = 0; j < 4; j++) lA[j] = *(const float4*)(ap + 4 * j);
    #pragma unroll
    for (int j = 0; j < 2; j++) { lG[j] = *(const float4*)(gp + 4 * j); lU[j] = *(const float4*)(up + 4 * j); }

    const int NC = HH / 32;
    for (int c = 0; c < NC; c++) {
        const int cur = c & 1;
        float* bA  = &sm[BUF_W + cur * BUFSTRIDE];
        float* bBg = bA + A_WORDS;
        float* bBu = bBg + 64 * STRIDE;
        // store current chunk
        #pragma unroll
        for (int j = 0; j < 4; j++) *(float4*)&bA[arow * STRIDE + aseg + 4 * j] = rna4(lA[j]);
        #pragma unroll
        for (int j = 0; j < 2; j++) {
            *(float4*)&bBg[brow * STRIDE + bseg + 4 * j] = rna4(lG[j]);
            *(float4*)&bBu[brow * STRIDE + bseg + 4 * j] = rna4(lU[j]);
        }
        __syncthreads();
        // issue next chunk's loads (overlap with mma)
        if (c + 1 < NC) {
            const int kb = (c + 1) * 32;
            #pragma unroll
            for (int j = 0; j < 4; j++) lA[j] = *(const float4*)(ap + kb + 4 * j);
            #pragma unroll
            for (int j = 0; j < 2; j++) { lG[j] = *(const float4*)(gp + kb + 4 * j); lU[j] = *(const float4*)(up + kb + 4 * j); }
        }
        // mma on current buffer
        const uint32_t bAa  = smb + (BUF_W + cur * BUFSTRIDE) * 4;
        const uint32_t bBga = bAa + A_WORDS * 4;
        const uint32_t bBua = bBga + 64 * STRIDE * 4;
        #pragma unroll
        for (int ks = 0; ks < 4; ks++) {
            uint32_t a[4][4], bg[4], bu[4];
            #pragma unroll
            for (int mi = 0; mi < 4; mi++)
                ldm_x4(a[mi], bAa + (uint32_t)(((wm * 64 + mi * 16) * STRIDE + ks * 8) * 4) + laneA);
            ldm_x4(bg, bBga + (uint32_t)((wn * 16 * STRIDE + ks * 8) * 4) + laneB);
            ldm_x4(bu, bBua + (uint32_t)((wn * 16 * STRIDE + ks * 8) * 4) + laneB);
            #pragma unroll
            for (int mi = 0; mi < 4; mi++)
                #pragma unroll
                for (int ni = 0; ni < 2; ni++) {
                    mma8(cg[mi][ni], a[mi], bg[2 * ni], bg[2 * ni + 1]);
                    mma8(cu[mi][ni], a[mi], bu[2 * ni], bu[2 * ni + 1]);
                }
        }
        __syncthreads();
    }

    // epilogue: h = relu(gate) * up * routing_weight
    const int g = lid >> 2, tq = lid & 3;
    #pragma unroll
    for (int mi = 0; mi < 4; mi++)
        #pragma unroll
        for (int b = 0; b < 2; b++) {
            const int row = wm * 64 + mi * 16 + g + 8 * b;
            if (row < rem) {
                const float w = swt[row];
                float* hp = &g_hbuf[(size_t)(base + row0 + row) * FF + f0];
                #pragma unroll
                for (int ni = 0; ni < 2; ni++) {
                    const int col = wn * 16 + ni * 8 + 2 * tq;
                    float2 o;
                    o.x = fmaxf(cg[mi][ni][2 * b + 0], 0.f) * cu[mi][ni][2 * b + 0] * w;
                    o.y = fmaxf(cg[mi][ni][2 * b + 1], 0.f) * cu[mi][ni][2 * b + 1] * w;
                    *(float2*)(hp + col) = o;
                }
            }
        }
}

// ---------------------------------------------------------------------------
// down GEMM (tf32 mma.sync): block = (expert, 128-slot tile, 128-h tile)
__global__ __launch_bounds__(256) void k_down(const float* __restrict__ wd,
                                              float* __restrict__ out) {
    extern __shared__ float sm[];
    const int e = blockIdx.x;
    const int n_e = g_cnt[e];
    const int row0 = blockIdx.y * 128;
    if (row0 >= n_e) return;
    const int base = g_off[e];
    int rem = n_e - row0; if (rem > 128) rem = 128;
    const int h0 = blockIdx.z * 128;
    const int tid = threadIdx.x;
    const int wid = tid >> 5, lid = tid & 31;
    const int wm = wid & 1, wn = wid >> 1;

    int* stok = (int*)&sm[STOK_W];
    if (tid < 128) {
        int m = tid < rem ? tid : rem - 1;
        stok[tid] = g_slot_tok[base + row0 + m];
    }
    __syncthreads();

    const int arow = tid >> 1, aseg = (tid & 1) * 16;   // A: 128 x 32
    const int ar = arow < rem ? arow : rem - 1;
    const float* ap = g_hbuf + (size_t)(base + row0 + ar) * FF + aseg;
    const float* bp = wd + ((size_t)e * HH + h0 + arow) * FF + aseg;  // B: 128 x 32, same mapping

    const uint32_t smb = smem_u32(sm);
    const int rl  = (lid & 7) + 8 * ((lid >> 3) & 1);
    const int clA = 4 * (lid >> 4);
    const uint32_t laneA = (uint32_t)(rl * STRIDE + clA) * 4;
    const int rbl = (lid & 7) + 8 * (lid >> 4);
    const int clB = 4 * ((lid >> 3) & 1);
    const uint32_t laneB = (uint32_t)(rbl * STRIDE + clB) * 4;

    float cc[4][4][4] = {};
    float4 lA[4], lB[4];
    #pragma unroll
    for (int j = 0; j < 4; j++) { lA[j] = *(const float4*)(ap + 4 * j); lB[j] = *(const float4*)(bp + 4 * j); }

    const int NC = FF / 32;
    for (int c = 0; c < NC; c++) {
        const int cur = c & 1;
        float* bA = &sm[BUF_W + cur * BUFSTRIDE];
        float* bB = bA + A_WORDS;
        #pragma unroll
        for (int j = 0; j < 4; j++) {
            *(float4*)&bA[arow * STRIDE + aseg + 4 * j] = rna4(lA[j]);
            *(float4*)&bB[arow * STRIDE + aseg + 4 * j] = rna4(lB[j]);
        }
        __syncthreads();
        if (c + 1 < NC) {
            const int kb = (c + 1) * 32;
            #pragma unroll
            for (int j = 0; j < 4; j++) { lA[j] = *(const float4*)(ap + kb + 4 * j); lB[j] = *(const float4*)(bp + kb + 4 * j); }
        }
        const uint32_t bAa = smb + (BUF_W + cur * BUFSTRIDE) * 4;
        const uint32_t bBa = bAa + A_WORDS * 4;
        #pragma unroll
        for (int ks = 0; ks < 4; ks++) {
            uint32_t a[4][4], bb[2][4];
            #pragma unroll
            for (int mi = 0; mi < 4; mi++)
                ldm_x4(a[mi], bAa + (uint32_t)(((wm * 64 + mi * 16) * STRIDE + ks * 8) * 4) + laneA);
            #pragma unroll
            for (int p = 0; p < 2; p++)
                ldm_x4(bb[p], bBa + (uint32_t)(((wn * 32 + p * 16) * STRIDE + ks * 8) * 4) + laneB);
            #pragma unroll
            for (int mi = 0; mi < 4; mi++)
                #pragma unroll
                for (int ni = 0; ni < 4; ni++)
                    mma8(cc[mi][ni], a[mi], bb[ni >> 1][2 * (ni & 1)], bb[ni >> 1][2 * (ni & 1) + 1]);
        }
        __syncthreads();
    }

    // epilogue: scatter-add to out
    const int g = lid >> 2, tq = lid & 3;
    #pragma unroll
    for (int mi = 0; mi < 4; mi++)
        #pragma unroll
        for (int b = 0; b < 2; b++) {
            const int row = wm * 64 + mi * 16 + g + 8 * b;
            if (row < rem) {
                float* op = out + (size_t)stok[row] * HH + h0;
                #pragma unroll
                for (int ni = 0; ni < 4; ni++) {
                    const int col = wn * 32 + ni * 8 + 2 * tq;
                    atomicAdd(op + col + 0, cc[mi][ni][2 * b + 0]);
                    atomicAdd(op + col + 1, cc[mi][ni][2 * b + 1]);
                }
            }
        }
}

// ---------------------------------------------------------------------------
extern "C" void kernel_launch(void* const* d_in, const int* in_sizes, int n_in,
                              void* d_out, int out_size) {
    const float* rin = (const float*)d_in[0];
    const float* hs  = (const float*)d_in[1];
    const float* wr  = (const float*)d_in[2];
    const float* wg  = (const float*)d_in[3];
    const float* wu  = (const float*)d_in[4];
    const float* wd  = (const float*)d_in[5];
    float* out    = (float*)d_out;
    float* logits = out + (size_t)TT * HH;

    cudaFuncSetAttribute(k_gateup, cudaFuncAttributeMaxDynamicSharedMemorySize, SMEM_BYTES);
    cudaFuncSetAttribute(k_down,   cudaFuncAttributeMaxDynamicSharedMemorySize, SMEM_BYTES);

    cudaMemsetAsync(out, 0, (size_t)TT * HH * sizeof(float), 0);
    k_init<<<1, 32>>>();
    k_router<<<TT, 128>>>(rin, wr, logits);
    k_scan<<<1, 32>>>();
    k_scatter<<<(TT + 255) / 256, 256>>>();
    k_gateup<<<dim3(EE, 16, FF / 64), 256, SMEM_BYTES>>>(hs, wg, wu);
    k_down<<<dim3(EE, 16, HH / 128), 256, SMEM_BYTES>>>(wd, out);
}